// round 2
// baseline (speedup 1.0000x reference)
#include <cuda_runtime.h>
#include <math.h>

#define NI 2304          // B*H*W
#define S_LEN 77
#define NQ 80            // N (query sequence)
#define HID 128
#define HEADS 8
#define DH 16
#define EPS 1e-6f

// Scratch (device globals: allocation-free per harness rules)
__device__ float g_K[NI * S_LEN * HID];   // feature-mapped K
__device__ float g_V[NI * S_LEN * HID];   // raw V (no /S; factors cancel)
__device__ float g_Q[NI * NQ * HID];      // feature-mapped Q

__device__ __forceinline__ float fmap(float t) {
    // elu(t)+1 with alpha=1
    return t > 0.0f ? t + 1.0f : expf(t);
}

// ---------------------------------------------------------------------------
// Tiled fp32 GEMM: C(M x 128) = gather(A)(M x KDEPTH) * W(KDEPTH x 128) + bias
// MODE 0: A = [x | guidance] (row m = flat n*S+s), out = g_K, fmap epilogue
// MODE 1: A = x,                                    out = g_V, no fmap
// MODE 2: A = query gathered (row m = ni*NQ+l),     out = g_Q, fmap epilogue
// Block: 128 rows x 128 cols, 256 threads, 8x8 register tile, k-chunk 16.
// M must be a multiple of 128 (177408 = 1386*128, 184320 = 1440*128).
// ---------------------------------------------------------------------------
template<int KDEPTH, int MODE>
__global__ __launch_bounds__(256, 2)
void gemm_kernel(const float* __restrict__ A1, const float* __restrict__ A2,
                 const float* __restrict__ Wm, const float* __restrict__ bias)
{
    __shared__ float As[16][128];   // [k][m]
    __shared__ float Bs[16][128];   // [k][n]

    float* outp = (MODE == 0) ? g_K : (MODE == 1 ? g_V : g_Q);

    const int t       = threadIdx.x;
    const int m0      = blockIdx.x * 128;
    const int m_local = t & 127;
    const int kblk    = (t >> 7) * 8;        // 0 or 8
    const int m       = m0 + m_local;

    // Row base pointer(s) for this thread's A-load row
    const float* arow;
    if (MODE == 2) {
        int ni  = m / NQ;
        int l   = m - ni * NQ;
        int b   = ni / 576;          // H*W = 576
        int rem = ni - b * 576;      // h*24 + w
        // query index: ((b*NQ + l)*576 + rem)*256
        arow = A1 + (size_t)((b * NQ + l) * 576 + rem) * 256;
    } else {
        arow = A1 + (size_t)m * 128;
    }
    const float* arow2 = (MODE == 0) ? (A2 + (size_t)m * 128) : A1;

    const int tm = t & 15;    // row-tile index
    const int tn = t >> 4;    // col-tile index

    float acc[8][8];
    #pragma unroll
    for (int i = 0; i < 8; i++)
        #pragma unroll
        for (int j = 0; j < 8; j++)
            acc[i][j] = 0.0f;

    const int bkk = t >> 4;            // 0..15
    const int bc8 = (t & 15) * 8;      // 0,8,...,120

    for (int k0 = 0; k0 < KDEPTH; k0 += 16) {
        // ---- global loads into registers (overlap with prior compute) ----
        const int cbase = k0 + kblk;
        const float* src;
        if (MODE == 0)
            src = (cbase >= 128) ? (arow2 + (cbase - 128)) : (arow + cbase);
        else
            src = arow + cbase;
        const float4 a0 = *(const float4*)(src);
        const float4 a1 = *(const float4*)(src + 4);
        const float4 b0 = *(const float4*)(Wm + (size_t)(k0 + bkk) * 128 + bc8);
        const float4 b1 = *(const float4*)(Wm + (size_t)(k0 + bkk) * 128 + bc8 + 4);

        __syncthreads();   // previous chunk's compute done
        As[kblk + 0][m_local] = a0.x;
        As[kblk + 1][m_local] = a0.y;
        As[kblk + 2][m_local] = a0.z;
        As[kblk + 3][m_local] = a0.w;
        As[kblk + 4][m_local] = a1.x;
        As[kblk + 5][m_local] = a1.y;
        As[kblk + 6][m_local] = a1.z;
        As[kblk + 7][m_local] = a1.w;
        *(float4*)&Bs[bkk][bc8]     = b0;
        *(float4*)&Bs[bkk][bc8 + 4] = b1;
        __syncthreads();

        // ---- 8x8 register-tile rank-16 update ----
        #pragma unroll
        for (int kk = 0; kk < 16; kk++) {
            float a[8], b[8];
            *(float4*)&a[0] = *(const float4*)&As[kk][tm * 8];
            *(float4*)&a[4] = *(const float4*)&As[kk][tm * 8 + 4];
            *(float4*)&b[0] = *(const float4*)&Bs[kk][tn * 8];
            *(float4*)&b[4] = *(const float4*)&Bs[kk][tn * 8 + 4];
            #pragma unroll
            for (int i = 0; i < 8; i++)
                #pragma unroll
                for (int j = 0; j < 8; j++)
                    acc[i][j] += a[i] * b[j];
        }
    }

    // ---- epilogue: bias (+ feature map), vectorized store ----
    float bvals[8];
    #pragma unroll
    for (int j = 0; j < 8; j++) bvals[j] = bias[tn * 8 + j];

    #pragma unroll
    for (int i = 0; i < 8; i++) {
        const int row = m0 + tm * 8 + i;
        float vals[8];
        #pragma unroll
        for (int j = 0; j < 8; j++) {
            float v = acc[i][j] + bvals[j];
            if (MODE != 1) v = fmap(v);
            vals[j] = v;
        }
        float* dst = outp + (size_t)row * 128 + tn * 8;
        *(float4*)dst       = *(float4*)&vals[0];
        *(float4*)(dst + 4) = *(float4*)&vals[4];
    }
}

// ---------------------------------------------------------------------------
// Attention reduction: 1 block per n, 128 threads (t = h*16 + dv).
// Pass 1 over S: Ksum[j] and per-head KV[d][dv] in registers.
// Pass 2 over l: Z = 1/(Q.Ksum + eps), out += (Q.KV)*Z ; final /NQ.
// ---------------------------------------------------------------------------
__global__ __launch_bounds__(128)
void attn_kernel(float* __restrict__ out)
{
    __shared__ float KV_s[HID * DH];    // [ (h*16+d) * 16 + dv ]
    __shared__ float Ksum_s[HID];
    __shared__ float Qs[HID];

    const int n  = blockIdx.x;
    const int t  = threadIdx.x;     // 0..127
    const int h  = t >> 4;
    const int dv = t & 15;

    const float* Kp = g_K + (size_t)n * (S_LEN * HID);
    const float* Vp = g_V + (size_t)n * (S_LEN * HID);

    float kv[16];
    #pragma unroll
    for (int j = 0; j < 16; j++) kv[j] = 0.0f;
    float ksum = 0.0f;

    for (int s = 0; s < S_LEN; s++) {
        const float kd = Kp[s * HID + t];          // coalesced
        ksum += kd;
        const float* vrow = Vp + s * HID + h * 16; // broadcast within head group
        const float4 v0 = *(const float4*)(vrow);
        const float4 v1 = *(const float4*)(vrow + 4);
        const float4 v2 = *(const float4*)(vrow + 8);
        const float4 v3 = *(const float4*)(vrow + 12);
        kv[0]  += kd * v0.x;  kv[1]  += kd * v0.y;
        kv[2]  += kd * v0.z;  kv[3]  += kd * v0.w;
        kv[4]  += kd * v1.x;  kv[5]  += kd * v1.y;
        kv[6]  += kd * v1.z;  kv[7]  += kd * v1.w;
        kv[8]  += kd * v2.x;  kv[9]  += kd * v2.y;
        kv[10] += kd * v2.z;  kv[11] += kd * v2.w;
        kv[12] += kd * v3.x;  kv[13] += kd * v3.y;
        kv[14] += kd * v3.z;  kv[15] += kd * v3.w;
    }
    Ksum_s[t] = ksum;
    #pragma unroll
    for (int j = 0; j < 16; j++)
        KV_s[t * 16 + j] = kv[j];   // thread t = (h, d) owns KV[h][d][*]

    float acc = 0.0f;
    const float* Qbase = g_Q + (size_t)n * (NQ * HID);
    const int hb = h * 16;

    for (int l = 0; l < NQ; l++) {
        __syncthreads();                 // prior reads of Qs done (and KV ready at l=0)
        Qs[t] = Qbase[l * HID + t];      // coalesced
        __syncthreads();
        float zs = EPS, tmp = 0.0f;
        #pragma unroll
        for (int d = 0; d < 16; d++) {
            const float qd = Qs[hb + d];
            zs  += qd * Ksum_s[hb + d];
            tmp += qd * KV_s[(hb + d) * 16 + dv];
        }
        acc += tmp / zs;
    }

    out[(size_t)n * HID + t] = acc * (1.0f / NQ);
}

// ---------------------------------------------------------------------------
extern "C" void kernel_launch(void* const* d_in, const int* in_sizes, int n_in,
                              void* d_out, int out_size)
{
    const float* query = (const float*)d_in[0];
    const float* x     = (const float*)d_in[1];
    const float* guid  = (const float*)d_in[2];
    const float* Wq    = (const float*)d_in[3];
    const float* bq    = (const float*)d_in[4];
    const float* Wk    = (const float*)d_in[5];
    const float* bk    = (const float*)d_in[6];
    const float* Wv    = (const float*)d_in[7];
    const float* bv    = (const float*)d_in[8];
    float* out = (float*)d_out;

    // K projection: (NI*S_LEN) x 256 @ Wk -> fmap -> g_K   (177408 rows = 1386*128)
    gemm_kernel<256, 0><<<1386, 256>>>(x, guid, Wk, bk);
    // V projection: (NI*S_LEN) x 128 @ Wv -> g_V
    gemm_kernel<128, 1><<<1386, 256>>>(x, nullptr, Wv, bv);
    // Q projection: (NI*NQ) x 256 @ Wq -> fmap -> g_Q      (184320 rows = 1440*128)
    gemm_kernel<256, 2><<<1440, 256>>>(query, nullptr, Wq, bq);
    // Attention reduction -> out (NI x 128)
    attn_kernel<<<NI, 128>>>(out);
}